// round 1
// baseline (speedup 1.0000x reference)
#include <cuda_runtime.h>

#define HD    64
#define LSEQ  2048
#define BATCH 16
#define NTOK  (BATCH * LSEQ)
#define NSTEP (LSEQ - 1)   // 2047 scan steps

// Scratch (device globals: allocation-free)
__device__ float g_h[NTOK * HD];     // post-LN hidden states (8 MB)
__device__ float g_invd[NTOK];       // 1 / (||h||^2 + 1e-6) per token

// ---------------- packed f32x2 helpers (sm_103a) ----------------
__device__ __forceinline__ unsigned long long ffma2(unsigned long long a,
                                                    unsigned long long b,
                                                    unsigned long long c) {
    unsigned long long d;
    asm("fma.rn.f32x2 %0, %1, %2, %3;" : "=l"(d) : "l"(a), "l"(b), "l"(c));
    return d;
}
__device__ __forceinline__ unsigned long long fadd2(unsigned long long a,
                                                    unsigned long long b) {
    unsigned long long d;
    asm("add.rn.f32x2 %0, %1, %2;" : "=l"(d) : "l"(a), "l"(b));
    return d;
}
__device__ __forceinline__ unsigned long long fpack2(float lo, float hi) {
    unsigned long long d;
    asm("mov.b64 %0, {%1, %2};" : "=l"(d) : "f"(lo), "f"(hi));
    return d;
}
__device__ __forceinline__ void funpack2(unsigned long long v, float& lo, float& hi) {
    asm("mov.b64 {%0, %1}, %2;" : "=f"(lo), "=f"(hi) : "l"(v));
}

// ---------------------------------------------------------------
// Phase 1: h = LN(embed[seq] + MLP(embed[seq])), plus inv_denom.
// One warp per token. W1/W2 live in dynamic shared (64 KB).
// ---------------------------------------------------------------
__global__ __launch_bounds__(256) void phase1_kernel(
    const int*   __restrict__ seq,
    const float* __restrict__ embed,
    const float* __restrict__ W1,
    const float* __restrict__ b1,
    const float* __restrict__ W2,
    const float* __restrict__ b2,
    const float* __restrict__ gamma,
    const float* __restrict__ beta)
{
    extern __shared__ float dsm[];
    float* W1s = dsm;            // 64*128
    float* W2s = dsm + 64 * 128; // 128*64

    __shared__ __align__(16) float b1s[128];
    __shared__ float b2s[64], gs[64], bs[64];
    __shared__ __align__(16) float hs[8][64];
    __shared__ __align__(16) float as_[8][128];

    const int tid = threadIdx.x;
    for (int i = tid; i < 64 * 128; i += 256) W1s[i] = W1[i];
    for (int i = tid; i < 128 * 64; i += 256) W2s[i] = W2[i];
    if (tid < 128) b1s[tid] = b1[tid];
    if (tid < 64) { b2s[tid] = b2[tid]; gs[tid] = gamma[tid]; bs[tid] = beta[tid]; }
    __syncthreads();

    const int w    = tid >> 5;
    const int lane = tid & 31;
    const int gw   = blockIdx.x * 8 + w;
    const int nw   = gridDim.x * 8;

    for (int tok = gw; tok < NTOK; tok += nw) {
        const int v = seq[tok];
        // embed gather -> shared (embed is 16 KB, stays hot in L1/L2)
        const float h0 = embed[v * 64 + lane];
        const float h1 = embed[v * 64 + 32 + lane];
        hs[w][lane]      = h0;
        hs[w][lane + 32] = h1;
        __syncwarp();

        // layer 1: a[m] = relu(sum_j h[j]*W1[j,m] + b1[m]); lane owns m = 4*lane..4*lane+3
        float4 a4 = *(const float4*)&b1s[lane * 4];
        #pragma unroll 16
        for (int j = 0; j < 64; j++) {
            const float  hj = hs[w][j];
            const float4 w4 = *(const float4*)&W1s[j * 128 + lane * 4];
            a4.x = fmaf(hj, w4.x, a4.x);
            a4.y = fmaf(hj, w4.y, a4.y);
            a4.z = fmaf(hj, w4.z, a4.z);
            a4.w = fmaf(hj, w4.w, a4.w);
        }
        a4.x = fmaxf(a4.x, 0.f); a4.y = fmaxf(a4.y, 0.f);
        a4.z = fmaxf(a4.z, 0.f); a4.w = fmaxf(a4.w, 0.f);
        *(float4*)&as_[w][lane * 4] = a4;
        __syncwarp();

        // layer 2: ff[i] = sum_m a[m]*W2[m,i] + b2[i]; lane owns i = 2*lane, 2*lane+1
        float f0 = b2s[2 * lane], f1 = b2s[2 * lane + 1];
        #pragma unroll 16
        for (int m = 0; m < 128; m++) {
            const float  am = as_[w][m];
            const float2 w2 = *(const float2*)&W2s[m * 64 + lane * 2];
            f0 = fmaf(am, w2.x, f0);
            f1 = fmaf(am, w2.y, f1);
        }

        // residual + LayerNorm
        float x0 = hs[w][2 * lane]     + f0;
        float x1 = hs[w][2 * lane + 1] + f1;

        float s = x0 + x1;
        #pragma unroll
        for (int o = 16; o > 0; o >>= 1) s += __shfl_xor_sync(0xffffffffu, s, o);
        const float mu = s * (1.0f / 64.0f);
        const float d0 = x0 - mu, d1 = x1 - mu;
        float sq = d0 * d0 + d1 * d1;
        #pragma unroll
        for (int o = 16; o > 0; o >>= 1) sq += __shfl_xor_sync(0xffffffffu, sq, o);
        const float rstd = rsqrtf(sq * (1.0f / 64.0f) + 1e-5f);

        const float y0 = d0 * rstd * gs[2 * lane]     + bs[2 * lane];
        const float y1 = d1 * rstd * gs[2 * lane + 1] + bs[2 * lane + 1];
        *(float2*)&g_h[tok * 64 + 2 * lane] = make_float2(y0, y1);

        float ss = y0 * y0 + y1 * y1;
        #pragma unroll
        for (int o = 16; o > 0; o >>= 1) ss += __shfl_xor_sync(0xffffffffu, ss, o);
        if (lane == 0) g_invd[tok] = 1.0f / (ss + 1e-6f);
        __syncwarp();
    }
}

// ---------------------------------------------------------------
// Phase 2: per-batch sequential delta-rule scan + output projections.
// One block per batch, 64 threads; thread i owns row M[i][0:64]
// packed as 32 f32x2 registers. Double-buffered k in shared with
// 2-step-deep global prefetch.
// ---------------------------------------------------------------
__device__ __forceinline__ float dot_row2(const unsigned long long* M2,
                                          const unsigned long long* k2) {
    unsigned long long a0 = 0ull, a1 = 0ull, a2 = 0ull, a3 = 0ull;
    #pragma unroll
    for (int j = 0; j < 32; j += 4) {
        a0 = ffma2(M2[j + 0], k2[j + 0], a0);
        a1 = ffma2(M2[j + 1], k2[j + 1], a1);
        a2 = ffma2(M2[j + 2], k2[j + 2], a2);
        a3 = ffma2(M2[j + 3], k2[j + 3], a3);
    }
    const unsigned long long s = fadd2(fadd2(a0, a1), fadd2(a2, a3));
    float lo, hi;
    funpack2(s, lo, hi);
    return lo + hi;
}

__global__ __launch_bounds__(64) void scan_kernel(
    const float* __restrict__ Wr, const float* __restrict__ br,
    const float* __restrict__ Wo, const float* __restrict__ bo,
    float* __restrict__ out)
{
    const int b   = blockIdx.x;
    const int tid = threadIdx.x;
    const float* hb  = g_h    + (size_t)b * LSEQ * HD;
    const float* idb = g_invd + (size_t)b * LSEQ;

    __shared__ __align__(16) float ks[2][64];
    __shared__ float cs[64], rs[64];

    unsigned long long M2[32];
    #pragma unroll
    for (int j = 0; j < 32; j++) M2[j] = 0ull;

    // software pipeline: kcur = element t, kA = element t+1 (pending store)
    float kcur = hb[tid];
    ks[0][tid] = kcur;
    float invd = idb[0];
    float kA   = hb[64 + tid];
    float iA   = idb[1];
    __syncthreads();

    for (int t = 0; t < NSTEP; ++t) {
        // prefetch element t+2 (2-step lead hides L2 latency)
        float kB = 0.0f, iB = 0.0f;
        if (t + 2 < LSEQ) {
            kB = hb[(t + 2) * 64 + tid];
            iB = idb[t + 2];
        }

        const unsigned long long* k2 =
            (const unsigned long long*)ks[t & 1];

        // v_pred[i] = M[i,:] . k   (packed even/odd accumulators)
        const float vp = dot_row2(M2, k2);
        const float dv = kcur - vp * invd;           // MEM_SCALE = 1
        const unsigned long long dv2 = fpack2(dv, dv);

        // M[i,:] += dv[i] * k   (re-read k from shared; fully independent FMAs)
        #pragma unroll
        for (int j = 0; j < 32; j++) M2[j] = ffma2(dv2, k2[j], M2[j]);

        // publish element t+1 into the other buffer
        ks[(t & 1) ^ 1][tid] = kA;
        kcur = kA; invd = iA;
        kA = kB;   iA = iB;
        __syncthreads();
    }

    // q = h[:, L-1]  lives in ks[(NSTEP) & 1] == ks[1]
    const unsigned long long* q2 = (const unsigned long long*)ks[NSTEP & 1];
    const float ctx = dot_row2(M2, q2);

    // out = (ctx @ Wr + br) @ Wo + bo
    cs[tid] = ctx;
    __syncthreads();
    float r = br[tid];
    #pragma unroll 8
    for (int j = 0; j < 64; j++) r = fmaf(cs[j], Wr[j * 64 + tid], r);
    rs[tid] = r;
    __syncthreads();
    float o = bo[tid];
    #pragma unroll 8
    for (int j = 0; j < 64; j++) o = fmaf(rs[j], Wo[j * 64 + tid], o);
    out[b * 64 + tid] = o;
}

// ---------------------------------------------------------------
extern "C" void kernel_launch(void* const* d_in, const int* in_sizes, int n_in,
                              void* d_out, int out_size)
{
    const int*   seq   = (const int*)  d_in[0];
    const float* embed = (const float*)d_in[1];
    const float* W1    = (const float*)d_in[2];
    const float* b1    = (const float*)d_in[3];
    const float* W2    = (const float*)d_in[4];
    const float* b2    = (const float*)d_in[5];
    const float* gamma = (const float*)d_in[6];
    const float* beta  = (const float*)d_in[7];
    const float* Wr    = (const float*)d_in[8];
    const float* br    = (const float*)d_in[9];
    const float* Wo    = (const float*)d_in[10];
    const float* bo    = (const float*)d_in[11];
    float* out = (float*)d_out;

    (void)in_sizes; (void)n_in; (void)out_size;

    cudaFuncSetAttribute(phase1_kernel,
                         cudaFuncAttributeMaxDynamicSharedMemorySize, 65536);
    phase1_kernel<<<296, 256, 65536>>>(seq, embed, W1, b1, W2, b2, gamma, beta);
    scan_kernel<<<BATCH, 64>>>(Wr, br, Wo, bo, out);
}